// round 9
// baseline (speedup 1.0000x reference)
#include <cuda_runtime.h>
#include <cstdint>

// MeanAggregator: multi-pass L2 temporal blocking, 8 nodes per warp.
// out[b,:] = mean_k table[neighs[b,k],:], B=50000, K=32, table 500000x128 f32.
//
// 4 launches; pass p gathers only rows in segment [p*125K,(p+1)*125K) (64MB,
// L2-resident together with out 26MB + idx 13MB). Kernel boundary = the global
// sweep barrier (R6 lesson). Each warp owns 8 nodes (2 groups of 4) -> 64
// expected rows/warp/pass, grid 782 blocks (~1-2 waves), pair-interleaved
// ballot compaction -> 4 independent LDG.128 gathers in flight per step.

#define BATCH   50000
#define DEGREE  32
#define D_FEAT  128
#define WARPS_PER_BLOCK 8
#define THREADS 256
#define NODES   8          // nodes per warp
#define GROUP   4          // nodes processed together (register cap)
#define NSEG    4
#define SEG     (500000 / NSEG)
#define FULL    0xffffffffu

__device__ int g_idx_is64;

// int64 indices in [0,500000) have all odd 32-bit words == 0; int32 data has
// random values there (P(128 zeros) ~ 0).
__global__ void detect_idx_dtype(const unsigned int* __restrict__ n32)
{
    bool all_zero = true;
    #pragma unroll
    for (int i = 1; i < 256; i += 2) {
        if (n32[i] != 0u) { all_zero = false; break; }
    }
    g_idx_is64 = all_zero ? 1 : 0;
}

__device__ __forceinline__ int popbit(unsigned& m)
{
    if (!m) return -1;
    const int b = __ffs(m) - 1;
    m &= (m - 1);
    return b;
}

__global__ __launch_bounds__(THREADS)
void mean_agg_pass(const void* __restrict__ neighs_raw,
                   const float4* __restrict__ table,  // [500000, 32] float4
                   float4* __restrict__ out,          // [50000, 32] float4 (raw sums until last pass)
                   int pass)
{
    const int gwarp = (blockIdx.x * THREADS + threadIdx.x) >> 5;
    const int lane  = threadIdx.x & 31;
    if (gwarp * NODES >= BATCH) return;          // 50000 % 8 == 0: full warps only

    const int base = gwarp * NODES;
    const int lo = pass * SEG;
    const int hi = lo + SEG;

    #pragma unroll 1
    for (int g = 0; g < NODES / GROUP; ++g) {
        const int nb = base + g * GROUP;

        // 4 coalesced idx loads (independent, MLP=4). Values < 500000 -> int.
        int idx[GROUP];
        #pragma unroll
        for (int n = 0; n < GROUP; ++n) {
            if (g_idx_is64) {
                idx[n] = (int)__ldg(&((const long long*)neighs_raw)
                                    [(size_t)(nb + n) * DEGREE + lane]);
            } else {
                idx[n] = __ldg(&((const int*)neighs_raw)
                               [(size_t)(nb + n) * DEGREE + lane]);
            }
        }

        unsigned bal[GROUP];
        #pragma unroll
        for (int n = 0; n < GROUP; ++n)
            bal[n] = __ballot_sync(FULL, idx[n] >= lo && idx[n] < hi);

        float4 acc[GROUP];
        #pragma unroll
        for (int n = 0; n < GROUP; ++n)
            acc[n] = make_float4(0.f, 0.f, 0.f, 0.f);

        // Pair-interleaved compaction: 2 rows from each of 2 nodes per step ->
        // 4 independent gathers into independent accumulators.
        #pragma unroll
        for (int p2 = 0; p2 < GROUP / 2; ++p2) {
            unsigned m0 = bal[2 * p2];
            unsigned m1 = bal[2 * p2 + 1];
            while (m0 | m1) {
                const int a0 = popbit(m0), a1 = popbit(m0);
                const int b0 = popbit(m1), b1 = popbit(m1);

                const int ia0 = __shfl_sync(FULL, idx[2 * p2],     a0 < 0 ? 0 : a0);
                const int ia1 = __shfl_sync(FULL, idx[2 * p2],     a1 < 0 ? 0 : a1);
                const int ib0 = __shfl_sync(FULL, idx[2 * p2 + 1], b0 < 0 ? 0 : b0);
                const int ib1 = __shfl_sync(FULL, idx[2 * p2 + 1], b1 < 0 ? 0 : b1);

                float4 v0, v1, v2, v3;
                if (a0 >= 0) v0 = __ldg(&table[(size_t)ia0 * (D_FEAT / 4) + lane]);
                if (a1 >= 0) v1 = __ldg(&table[(size_t)ia1 * (D_FEAT / 4) + lane]);
                if (b0 >= 0) v2 = __ldg(&table[(size_t)ib0 * (D_FEAT / 4) + lane]);
                if (b1 >= 0) v3 = __ldg(&table[(size_t)ib1 * (D_FEAT / 4) + lane]);

                if (a0 >= 0) { acc[2*p2].x   += v0.x; acc[2*p2].y   += v0.y; acc[2*p2].z   += v0.z; acc[2*p2].w   += v0.w; }
                if (a1 >= 0) { acc[2*p2].x   += v1.x; acc[2*p2].y   += v1.y; acc[2*p2].z   += v1.z; acc[2*p2].w   += v1.w; }
                if (b0 >= 0) { acc[2*p2+1].x += v2.x; acc[2*p2+1].y += v2.y; acc[2*p2+1].z += v2.z; acc[2*p2+1].w += v2.w; }
                if (b1 >= 0) { acc[2*p2+1].x += v3.x; acc[2*p2+1].y += v3.y; acc[2*p2+1].z += v3.z; acc[2*p2+1].w += v3.w; }
            }
        }

        // Out RMW: partial sums stay L2-resident across passes (write-back).
        #pragma unroll
        for (int n = 0; n < GROUP; ++n) {
            float4* o = &out[(size_t)(nb + n) * (D_FEAT / 4) + lane];
            float4 a = acc[n];
            if (pass != 0) {
                const float4 p = *o;
                a.x += p.x; a.y += p.y; a.z += p.z; a.w += p.w;
            }
            if (pass == NSEG - 1) {
                const float s = 1.0f / (float)DEGREE;
                a.x *= s; a.y *= s; a.z *= s; a.w *= s;
            }
            *o = a;
        }
    }
}

extern "C" void kernel_launch(void* const* d_in, const int* in_sizes, int n_in,
                              void* d_out, int out_size)
{
    const void*   neighs = d_in[0];
    const float4* table  = (const float4*)d_in[1];
    float4*       out    = (float4*)d_out;

    detect_idx_dtype<<<1, 1>>>((const unsigned int*)neighs);

    const int warps_needed = BATCH / NODES;                       // 6250
    const int blocks = (warps_needed + WARPS_PER_BLOCK - 1) / WARPS_PER_BLOCK;  // 782
    for (int p = 0; p < NSEG; ++p)
        mean_agg_pass<<<blocks, THREADS>>>(neighs, table, out, p);
}